// round 13
// baseline (speedup 1.0000x reference)
#include <cuda_runtime.h>
#include <cuda_bf16.h>
#include <math.h>
#include <stdint.h>

#define BB   8
#define SS   2048
#define DD   768
#define HH   8
#define HDIM 96
#define M_ROWS (BB*SS)

// Scratch (allocation-free rule: __device__ globals)
__device__ __nv_bfloat16 g_Xb[(size_t)M_ROWS * DD];
__device__ __nv_bfloat16 g_Wb[3][(size_t)DD * DD];
__device__ __nv_bfloat16 g_QKV[3][(size_t)BB * HH * SS * HDIM]; // Q(scaled*log2e),K,V
__device__ uint32_t      g_adjbits[(size_t)BB * SS * (SS / 32)]; // 1 bit per adj entry
__device__ float         g_C[(size_t)BB * SS * DD];              // attention context

// ---------------------------------------------------------------------------
// Helpers
// ---------------------------------------------------------------------------
__device__ __forceinline__ uint32_t smem_u32(const void* p) {
    return (uint32_t)__cvta_generic_to_shared(p);
}
__device__ __forceinline__ void cp16(uint32_t dst, const void* src) {
    asm volatile("cp.async.cg.shared.global [%0], [%1], 16;\n" :: "r"(dst), "l"(src));
}
__device__ __forceinline__ void cp_commit() { asm volatile("cp.async.commit_group;\n"); }
__device__ __forceinline__ void cp_wait0()  { asm volatile("cp.async.wait_group 0;\n"); }

__device__ __forceinline__ void mma_bf16(float d[4],
                                         const uint32_t a[4],
                                         const uint32_t b0, const uint32_t b1) {
    asm volatile(
        "mma.sync.aligned.m16n8k16.row.col.f32.bf16.bf16.f32 "
        "{%0,%1,%2,%3}, {%4,%5,%6,%7}, {%8,%9}, {%0,%1,%2,%3};\n"
        : "+f"(d[0]), "+f"(d[1]), "+f"(d[2]), "+f"(d[3])
        : "r"(a[0]), "r"(a[1]), "r"(a[2]), "r"(a[3]), "r"(b0), "r"(b1));
}

__device__ __forceinline__ void ldsm_x4(uint32_t& r0, uint32_t& r1,
                                        uint32_t& r2, uint32_t& r3, uint32_t addr) {
    asm volatile(
        "ldmatrix.sync.aligned.m8n8.x4.shared.b16 {%0,%1,%2,%3}, [%4];"
        : "=r"(r0), "=r"(r1), "=r"(r2), "=r"(r3) : "r"(addr));
}
__device__ __forceinline__ void ldsm_x4_t(uint32_t& r0, uint32_t& r1,
                                          uint32_t& r2, uint32_t& r3, uint32_t addr) {
    asm volatile(
        "ldmatrix.sync.aligned.m8n8.x4.trans.shared.b16 {%0,%1,%2,%3}, [%4];"
        : "=r"(r0), "=r"(r1), "=r"(r2), "=r"(r3) : "r"(addr));
}
__device__ __forceinline__ uint32_t packbf(float a, float b) {
    __nv_bfloat162 v = __float22bfloat162_rn(make_float2(a, b));
    return *reinterpret_cast<uint32_t*>(&v);
}
__device__ __forceinline__ uint2 cvt4(float4 v) {
    return make_uint2(packbf(v.x, v.y), packbf(v.z, v.w));
}

// ---------------------------------------------------------------------------
// Kernel 0a: fp32 -> bf16, 4 float4 per thread (MLP=4), 8B packed stores
// ---------------------------------------------------------------------------
__global__ void __launch_bounds__(256) conv_x_kernel(const float* __restrict__ src,
                                                     __nv_bfloat16* __restrict__ dst,
                                                     int n4) {
    int i0 = blockIdx.x * 1024 + threadIdx.x;
#pragma unroll
    for (int j = 0; j < 4; j++) {
        int i = i0 + j * 256;
        if (i < n4) {
            float4 v = reinterpret_cast<const float4*>(src)[i];
            reinterpret_cast<uint2*>(dst)[i] = cvt4(v);
        }
    }
}

// Merged W conversion: blockIdx.y selects Wq/Wk/Wv -> g_Wb[y]
__global__ void __launch_bounds__(256) conv_w_kernel(const float* __restrict__ Wq,
                                                     const float* __restrict__ Wk,
                                                     const float* __restrict__ Wv,
                                                     int n4) {
    const int z = blockIdx.y;
    const float* __restrict__ src = (z == 0) ? Wq : ((z == 1) ? Wk : Wv);
    __nv_bfloat16* __restrict__ dst = g_Wb[z];
    int i0 = blockIdx.x * 1024 + threadIdx.x;
#pragma unroll
    for (int j = 0; j < 4; j++) {
        int i = i0 + j * 256;
        if (i < n4) {
            float4 v = reinterpret_cast<const float4*>(src)[i];
            reinterpret_cast<uint2*>(dst)[i] = cvt4(v);
        }
    }
}

// ---------------------------------------------------------------------------
// Kernel 0b: pack adjacency int32 -> bitmask (warp ballot). One word / warp.
// ---------------------------------------------------------------------------
__global__ void __launch_bounds__(256) pack_adj_kernel(const int* __restrict__ adj) {
    size_t word = (size_t)blockIdx.x * 8 + (threadIdx.x >> 5);
    int lane = threadIdx.x & 31;
    int v = adj[word * 32 + lane];
    uint32_t m = __ballot_sync(0xFFFFFFFFu, v != 0);
    if (lane == 0) g_adjbits[word] = m;
}

// ---------------------------------------------------------------------------
// Kernel 1: QKV projection, bf16 mma + ldmatrix. Tile 128x128.
// K-superstage 64 (two 32-col half-blocks at 80B pitch), 2-stage, 12 iters.
// grid = (DD/128, M_ROWS/128, 3), block 256 (8 warps, warp 32x64).
// ---------------------------------------------------------------------------
#define QHALF_B 10240                 // 128 rows x 80 B : one 32-col half-block
#define Q_STAGE_B (2 * QHALF_B)       // 64-col superstage per array (20480 B)
#define Q_SMEM  (2 * 2 * Q_STAGE_B)   // 2 arrays x 2 stages = 81920 B

__global__ void __launch_bounds__(256, 2) qkv_gemm_kernel(
    const float* __restrict__ bq, const float* __restrict__ bk,
    const float* __restrict__ bv)
{
    extern __shared__ uint32_t qsm[];
    const uint32_t smb = smem_u32(qsm);

    const int z = blockIdx.z;
    const __nv_bfloat16* __restrict__ W = g_Wb[z];
    const float* __restrict__ bias = (z == 0) ? bq : ((z == 1) ? bk : bv);
    __nv_bfloat16* __restrict__ outp = g_QKV[z];
    // Q pre-scale folds 1/sqrt(96) AND log2(e) (softmax uses exp2)
    const float oscale = (z == 0)
        ? 0.10206207261596577f * 1.4426950408889634f : 1.0f;

    const int n0 = blockIdx.x * 128;
    const int m0 = blockIdx.y * 128;
    const int t  = threadIdx.x;
    const int w  = t >> 5;
    const int lane = t & 31;
    const int g  = lane >> 2;
    const int t4 = lane & 3;
    const int m0w = (w & 3) * 32;
    const int n0w = (w >> 2) * 64;

    const uint32_t lml = (uint32_t)((lane & 15) * 80 + ((lane >> 4) & 1) * 16);

    const int sr = t >> 1;           // row 0..127

    auto issue = [&](int k0, int buf) {
        uint32_t ab = smb + buf * 2 * Q_STAGE_B;   // stage holds A then B
        uint32_t bb = ab + Q_STAGE_B;
        const __nv_bfloat16* Ar = g_Xb + (size_t)(m0 + sr) * DD + k0;
        const __nv_bfloat16* Br = W    + (size_t)(n0 + sr) * DD + k0;
#pragma unroll
        for (int i = 0; i < 4; i++) {
            int c = (t & 1) * 4 + i;      // chunk 0..7
            int half = c >> 2, ch = c & 3;
            uint32_t off = (uint32_t)(half * QHALF_B + sr * 80 + ch * 16);
            int src = half * 32 + ch * 8;
            cp16(ab + off, Ar + src);
            cp16(bb + off, Br + src);
        }
        cp_commit();
    };

    float acc[2][8][4];
#pragma unroll
    for (int i = 0; i < 2; i++)
#pragma unroll
        for (int j = 0; j < 8; j++)
#pragma unroll
            for (int e = 0; e < 4; e++) acc[i][j][e] = 0.0f;

    const int NIT = DD / 64;  // 12
    issue(0, 0);

    for (int it = 0; it < NIT; it++) {
        cp_wait0();
        __syncthreads();
        if (it + 1 < NIT) issue((it + 1) * 64, (it + 1) & 1);

        const uint32_t xsb = smb + (it & 1) * 2 * Q_STAGE_B;
        const uint32_t wsb = xsb + Q_STAGE_B;

#pragma unroll
        for (int kb = 0; kb < 2; kb++) {
#pragma unroll
            for (int ks = 0; ks < 2; ks++) {
                uint32_t a[2][4];
#pragma unroll
                for (int i = 0; i < 2; i++) {
                    uint32_t addr = xsb + (uint32_t)(kb * QHALF_B +
                                    (m0w + 16 * i) * 80 + ks * 32) + lml;
                    ldsm_x4(a[i][0], a[i][1], a[i][2], a[i][3], addr);
                }
#pragma unroll
                for (int j2 = 0; j2 < 4; j2++) {
                    uint32_t r0, r1, r2, r3;
                    uint32_t addr = wsb + (uint32_t)(kb * QHALF_B +
                                    (n0w + 16 * j2) * 80 + ks * 32) + lml;
                    ldsm_x4(r0, r1, r2, r3, addr);
#pragma unroll
                    for (int i = 0; i < 2; i++) {
                        mma_bf16(acc[i][2 * j2],     a[i], r0, r2);
                        mma_bf16(acc[i][2 * j2 + 1], a[i], r1, r3);
                    }
                }
            }
        }
    }

    // Epilogue: bias, optional Q scale, pack bf16 pairs, write [B,H,S,HD]
#pragma unroll
    for (int i = 0; i < 2; i++) {
        int rA = m0 + m0w + i * 16 + g;
        int rB = rA + 8;
        int bA = rA >> 11, sA = rA & (SS - 1);
        int bBv = rB >> 11, sB = rB & (SS - 1);
#pragma unroll
        for (int j = 0; j < 8; j++) {
            int c = n0 + n0w + j * 8 + 2 * t4;
            int h = c / HDIM;
            int d = c - h * HDIM;
            float b0 = bias[c], b1 = bias[c + 1];
            uint32_t vA = packbf((acc[i][j][0] + b0) * oscale, (acc[i][j][1] + b1) * oscale);
            uint32_t vB = packbf((acc[i][j][2] + b0) * oscale, (acc[i][j][3] + b1) * oscale);
            *reinterpret_cast<uint32_t*>(
                outp + (((size_t)(bA * HH + h)) * SS + sA) * HDIM + d) = vA;
            *reinterpret_cast<uint32_t*>(
                outp + (((size_t)(bBv * HH + h)) * SS + sB) * HDIM + d) = vB;
        }
    }
}

// ---------------------------------------------------------------------------
// Kernel 2: FA flash attention with UNSHIFTED exp2 softmax (Q pre-scaled by
// log2e/sqrt(96); masked -> exp2(-1e9) = 0). Register P, bit mask.
// QT=128, KT=64, 2-stage cp.async, K via ldmatrix, V via ldmatrix.trans.
// grid = (SS/128, HH, BB), block 256, 2 CTAs/SM.
// ---------------------------------------------------------------------------
#define KPW 52                       // K/V smem pitch in words (208B row)
#define A_STAGE (2 * 64 * KPW)       // K + V words per stage
#define ATTN_BYTES (2 * A_STAGE * 4) // 53248

__global__ void __launch_bounds__(256, 2) attn_kernel()
{
    extern __shared__ uint32_t asm_[];
    const uint32_t smb = smem_u32(asm_);

    const int t    = threadIdx.x;
    const int w    = t >> 5;
    const int lane = t & 31;
    const int g    = lane >> 2;
    const int t4   = lane & 3;
    const int qt0  = blockIdx.x * 128;
    const int h    = blockIdx.y;
    const int b    = blockIdx.z;

    const __nv_bfloat16* __restrict__ Qb = g_QKV[0] + ((size_t)(b * HH + h)) * SS * HDIM;
    const __nv_bfloat16* __restrict__ Kb = g_QKV[1] + ((size_t)(b * HH + h)) * SS * HDIM;
    const __nv_bfloat16* __restrict__ Vb = g_QKV[2] + ((size_t)(b * HH + h)) * SS * HDIM;

    const int rAl = 16 * w + g;
    const int rBl = rAl + 8;
    const uint32_t* __restrict__ bitsA =
        g_adjbits + ((size_t)b * SS + qt0 + rAl) * (SS / 32);
    const uint32_t* __restrict__ bitsB =
        g_adjbits + ((size_t)b * SS + qt0 + rBl) * (SS / 32);

    // ---- Q fragments preloaded to registers (pre-scaled incl. log2e) ----
    uint32_t qa[6][4];
    {
        const uint32_t* qwA =
            reinterpret_cast<const uint32_t*>(Qb + (size_t)(qt0 + rAl) * HDIM);
        const uint32_t* qwB =
            reinterpret_cast<const uint32_t*>(Qb + (size_t)(qt0 + rBl) * HDIM);
#pragma unroll
        for (int ks = 0; ks < 6; ks++) {
            qa[ks][0] = qwA[8 * ks + t4];
            qa[ks][1] = qwB[8 * ks + t4];
            qa[ks][2] = qwA[8 * ks + 4 + t4];
            qa[ks][3] = qwB[8 * ks + 4 + t4];
        }
    }

    // ldmatrix lane offsets
    const uint32_t lmlK = (uint32_t)((lane & 15) * (KPW * 4) + ((lane >> 4) & 1) * 16);
    const int vk  = (lane & 7) + ((lane >> 3) & 1) * 8;
    const int vn  = ((lane >> 4) & 1) * 8;
    const uint32_t lmlV = (uint32_t)(vk * (KPW * 4) + vn * 2);

    float acc_o[12][4];
#pragma unroll
    for (int j = 0; j < 12; j++)
#pragma unroll
        for (int e = 0; e < 4; e++) acc_o[j][e] = 0.0f;
    float l0_ = 0.0f, l1_ = 0.0f;    // per-thread partial row sums

    auto issue = [&](int kt0, int buf) {
        uint32_t kb = smb + buf * A_STAGE * 4;
        uint32_t vb = kb + 64 * KPW * 4;
#pragma unroll
        for (int i = 0; i < 3; i++) {
            int e = t + i * 256;
            int r = e / 12, ch = e % 12;
            cp16(kb + r * (KPW * 4) + ch * 16, Kb + (size_t)(kt0 + r) * HDIM + ch * 8);
            cp16(vb + r * (KPW * 4) + ch * 16, Vb + (size_t)(kt0 + r) * HDIM + ch * 8);
        }
        cp_commit();
    };

    const int NKT = SS / 64;  // 32
    issue(0, 0);

    for (int kt = 0; kt < NKT; kt++) {
        cp_wait0();
        __syncthreads();
        if (kt + 1 < NKT) issue((kt + 1) * 64, (kt + 1) & 1);

        const uint32_t kbase = smb + (kt & 1) * A_STAGE * 4;
        const uint32_t vbase = kbase + 64 * KPW * 4 + lmlV;

        // mask bits (issued early; consumed after QK mma block)
        uint2 wA = *(const uint2*)(bitsA + 2 * kt);
        uint2 wB = *(const uint2*)(bitsB + 2 * kt);
        uint64_t bA = ((uint64_t)wA.y << 32) | wA.x;
        uint64_t bB = ((uint64_t)wB.y << 32) | wB.x;

        // ---- S = Q K^T : 16 rows x 64 keys per warp, 6 k16-steps ----
        float s_[8][4];
#pragma unroll
        for (int j = 0; j < 8; j++)
#pragma unroll
            for (int e = 0; e < 4; e++) s_[j][e] = 0.0f;

#pragma unroll
        for (int ks = 0; ks < 6; ks++) {
#pragma unroll
            for (int j2 = 0; j2 < 4; j2++) {
                uint32_t r0, r1, r2, r3;
                ldsm_x4(r0, r1, r2, r3,
                        kbase + (uint32_t)(16 * j2 * (KPW * 4) + ks * 32) + lmlK);
                mma_bf16(s_[2 * j2],     qa[ks], r0, r2);
                mma_bf16(s_[2 * j2 + 1], qa[ks], r1, r3);
            }
        }

        // ---- mask (bit extract) + unshifted exp2, packed in place ----
#pragma unroll
        for (int j = 0; j < 8; j++) {
            int sh = 8 * j + 2 * t4;
            if (!((bA >> sh) & 1))       s_[j][0] = -1e9f;
            if (!((bA >> (sh + 1)) & 1)) s_[j][1] = -1e9f;
            if (!((bB >> sh) & 1))       s_[j][2] = -1e9f;
            if (!((bB >> (sh + 1)) & 1)) s_[j][3] = -1e9f;
            float p0 = exp2f(s_[j][0]);
            float p1 = exp2f(s_[j][1]);
            float p2 = exp2f(s_[j][2]);
            float p3 = exp2f(s_[j][3]);
            l0_ += p0 + p1;
            l1_ += p2 + p3;
            s_[j][0] = __uint_as_float(packbf(p0, p1));
            s_[j][1] = __uint_as_float(packbf(p2, p3));
        }

        // ---- O += P V : P frags from score registers, V via ldmatrix.trans ----
#pragma unroll
        for (int ks = 0; ks < 4; ks++) {
            uint32_t a[4];
            a[0] = __float_as_uint(s_[2 * ks][0]);
            a[1] = __float_as_uint(s_[2 * ks][1]);
            a[2] = __float_as_uint(s_[2 * ks + 1][0]);
            a[3] = __float_as_uint(s_[2 * ks + 1][1]);
            uint32_t vrow = vbase + (uint32_t)(ks * 16 * KPW * 4);
#pragma unroll
            for (int j2 = 0; j2 < 6; j2++) {
                uint32_t v0, v1, v2, v3;
                ldsm_x4_t(v0, v1, v2, v3, vrow + j2 * 32);
                mma_bf16(acc_o[2 * j2],     a, v0, v1);
                mma_bf16(acc_o[2 * j2 + 1], a, v2, v3);
            }
        }
    }

    // ---- single end-of-loop row-sum reduction across the quad ----
    l0_ += __shfl_xor_sync(0xFFFFFFFFu, l0_, 1);
    l0_ += __shfl_xor_sync(0xFFFFFFFFu, l0_, 2);
    l1_ += __shfl_xor_sync(0xFFFFFFFFu, l1_, 1);
    l1_ += __shfl_xor_sync(0xFFFFFFFFu, l1_, 2);

    // ---- finalize: normalize and write context fp32 ----
    {
        float inv0 = 1.0f / l0_;
        float inv1 = 1.0f / l1_;
        float* oA = g_C + (size_t)(b * SS + qt0 + rAl) * DD + h * HDIM;
        float* oB = g_C + (size_t)(b * SS + qt0 + rBl) * DD + h * HDIM;
#pragma unroll
        for (int j = 0; j < 12; j++) {
            int c = j * 8 + 2 * t4;
            *reinterpret_cast<float2*>(oA + c) =
                make_float2(acc_o[j][0] * inv0, acc_o[j][1] * inv0);
            *reinterpret_cast<float2*>(oB + c) =
                make_float2(acc_o[j][2] * inv1, acc_o[j][3] * inv1);
        }
    }
}

// ---------------------------------------------------------------------------
// Kernel 3: residual + LayerNorm, float4 path, 2 rows per block.
// grid = 8192, block = 384 (warps 0-5 row0, warps 6-11 row1).
// ---------------------------------------------------------------------------
__global__ void __launch_bounds__(384) ln_kernel(
    const float* __restrict__ X,
    const float* __restrict__ gamma,
    const float* __restrict__ beta,
    float* __restrict__ out)
{
    const int t   = threadIdx.x;
    const int rsel = t / 192;             // 0 or 1
    const int tl  = t - rsel * 192;       // 0..191
    const int row = blockIdx.x * 2 + rsel;

    const float4* __restrict__ c4 = reinterpret_cast<const float4*>(g_C + (size_t)row * DD);
    const float4* __restrict__ x4 = reinterpret_cast<const float4*>(X  + (size_t)row * DD);

    float4 cv = c4[tl];
    float4 xv = x4[tl];
    float4 v = make_float4(cv.x + xv.x, cv.y + xv.y, cv.z + xv.z, cv.w + xv.w);
    float sum = v.x + v.y + v.z + v.w;
    float sq  = v.x * v.x + v.y * v.y + v.z * v.z + v.w * v.w;

#pragma unroll
    for (int o = 16; o > 0; o >>= 1) {
        sum += __shfl_xor_sync(0xFFFFFFFFu, sum, o);
        sq  += __shfl_xor_sync(0xFFFFFFFFu, sq, o);
    }
    __shared__ float rs_[12], rq_[12];
    int w = t >> 5, lane = t & 31;
    if (lane == 0) { rs_[w] = sum; rq_[w] = sq; }
    __syncthreads();
    sum = 0.0f; sq = 0.0f;
    int base = rsel * 6;
#pragma unroll
    for (int w2 = 0; w2 < 6; w2++) { sum += rs_[base + w2]; sq += rq_[base + w2]; }

    float mean = sum * (1.0f / 768.0f);
    float var  = sq * (1.0f / 768.0f) - mean * mean;
    float rstd = rsqrtf(var + 1e-5f);

    float4 gv = reinterpret_cast<const float4*>(gamma)[tl];
    float4 bv = reinterpret_cast<const float4*>(beta)[tl];
    float4 o;
    o.x = (v.x - mean) * rstd * gv.x + bv.x;
    o.y = (v.y - mean) * rstd * gv.y + bv.y;
    o.z = (v.z - mean) * rstd * gv.z + bv.z;
    o.w = (v.w - mean) * rstd * gv.w + bv.w;
    reinterpret_cast<float4*>(out + (size_t)row * DD)[tl] = o;
}

// ---------------------------------------------------------------------------
extern "C" void kernel_launch(void* const* d_in, const int* in_sizes, int n_in,
                              void* d_out, int out_size)
{
    const float* X     = (const float*)d_in[0];
    const int*   adj   = (const int*)  d_in[1];
    const float* Wq    = (const float*)d_in[2];
    const float* bq    = (const float*)d_in[3];
    const float* Wk    = (const float*)d_in[4];
    const float* bk    = (const float*)d_in[5];
    const float* Wv    = (const float*)d_in[6];
    const float* bv    = (const float*)d_in[7];
    const float* gamma = (const float*)d_in[8];
    const float* beta  = (const float*)d_in[9];
    float* out = (float*)d_out;

    __nv_bfloat16 *xb_p;
    cudaGetSymbolAddress((void**)&xb_p, g_Xb);

    const int nX4 = M_ROWS * DD / 4;   // 3,145,728
    const int nW4 = DD * DD / 4;       // 147,456
    conv_x_kernel<<<(nX4 + 1023) / 1024, 256>>>(X, xb_p, nX4);
    {
        dim3 gw((nW4 + 1023) / 1024, 3);
        conv_w_kernel<<<gw, 256>>>(Wq, Wk, Wv, nW4);
    }

    pack_adj_kernel<<<(BB * SS * (SS / 32)) / 8, 256>>>(adj);

    cudaFuncSetAttribute(qkv_gemm_kernel,
                         cudaFuncAttributeMaxDynamicSharedMemorySize, Q_SMEM);
    dim3 gg(DD / 128, M_ROWS / 128, 3);
    qkv_gemm_kernel<<<gg, 256, Q_SMEM>>>(bq, bk, bv);

    cudaFuncSetAttribute(attn_kernel,
                         cudaFuncAttributeMaxDynamicSharedMemorySize, ATTN_BYTES);
    dim3 ga(SS / 128, HH, BB);
    attn_kernel<<<ga, 256, ATTN_BYTES>>>();

    ln_kernel<<<M_ROWS / 2, 384>>>(X, gamma, beta, out);
}

// round 15
// speedup vs baseline: 1.1526x; 1.1526x over previous
#include <cuda_runtime.h>
#include <cuda_bf16.h>
#include <math.h>
#include <stdint.h>

#define BB   8
#define SS   2048
#define DD   768
#define HH   8
#define HDIM 96
#define M_ROWS (BB*SS)

// Scratch (allocation-free rule: __device__ globals)
__device__ __nv_bfloat16 g_Xb[(size_t)M_ROWS * DD];
__device__ __nv_bfloat16 g_Wb[3][(size_t)DD * DD];
__device__ __nv_bfloat16 g_QKV[3][(size_t)BB * HH * SS * HDIM]; // Q(scaled*log2e),K,V
__device__ uint32_t      g_adjbits[(size_t)BB * SS * (SS / 32)]; // 1 bit per adj entry
__device__ float         g_C[(size_t)BB * SS * DD];              // attention context

// ---------------------------------------------------------------------------
// Helpers
// ---------------------------------------------------------------------------
__device__ __forceinline__ uint32_t smem_u32(const void* p) {
    return (uint32_t)__cvta_generic_to_shared(p);
}
__device__ __forceinline__ void cp16(uint32_t dst, const void* src) {
    asm volatile("cp.async.cg.shared.global [%0], [%1], 16;\n" :: "r"(dst), "l"(src));
}
__device__ __forceinline__ void cp_commit() { asm volatile("cp.async.commit_group;\n"); }
__device__ __forceinline__ void cp_wait0()  { asm volatile("cp.async.wait_group 0;\n"); }

__device__ __forceinline__ void mma_bf16(float d[4],
                                         const uint32_t a[4],
                                         const uint32_t b0, const uint32_t b1) {
    asm volatile(
        "mma.sync.aligned.m16n8k16.row.col.f32.bf16.bf16.f32 "
        "{%0,%1,%2,%3}, {%4,%5,%6,%7}, {%8,%9}, {%0,%1,%2,%3};\n"
        : "+f"(d[0]), "+f"(d[1]), "+f"(d[2]), "+f"(d[3])
        : "r"(a[0]), "r"(a[1]), "r"(a[2]), "r"(a[3]), "r"(b0), "r"(b1));
}

__device__ __forceinline__ void ldsm_x4(uint32_t& r0, uint32_t& r1,
                                        uint32_t& r2, uint32_t& r3, uint32_t addr) {
    asm volatile(
        "ldmatrix.sync.aligned.m8n8.x4.shared.b16 {%0,%1,%2,%3}, [%4];"
        : "=r"(r0), "=r"(r1), "=r"(r2), "=r"(r3) : "r"(addr));
}
__device__ __forceinline__ void ldsm_x4_t(uint32_t& r0, uint32_t& r1,
                                          uint32_t& r2, uint32_t& r3, uint32_t addr) {
    asm volatile(
        "ldmatrix.sync.aligned.m8n8.x4.trans.shared.b16 {%0,%1,%2,%3}, [%4];"
        : "=r"(r0), "=r"(r1), "=r"(r2), "=r"(r3) : "r"(addr));
}
__device__ __forceinline__ uint32_t packbf(float a, float b) {
    __nv_bfloat162 v = __float22bfloat162_rn(make_float2(a, b));
    return *reinterpret_cast<uint32_t*>(&v);
}
__device__ __forceinline__ uint2 cvt4(float4 v) {
    return make_uint2(packbf(v.x, v.y), packbf(v.z, v.w));
}
// Guaranteed single-instruction MUFU.EX2 (ex2.approx.ftz); ex2(-1e9) -> 0.
__device__ __forceinline__ float ex2_fast(float x) {
    float r;
    asm("ex2.approx.ftz.f32 %0, %1;" : "=f"(r) : "f"(x));
    return r;
}

// ---------------------------------------------------------------------------
// Kernel 0a: fp32 -> bf16, 4 float4 per thread (MLP=4), 8B packed stores
// ---------------------------------------------------------------------------
__global__ void __launch_bounds__(256) conv_x_kernel(const float* __restrict__ src,
                                                     __nv_bfloat16* __restrict__ dst,
                                                     int n4) {
    int i0 = blockIdx.x * 1024 + threadIdx.x;
#pragma unroll
    for (int j = 0; j < 4; j++) {
        int i = i0 + j * 256;
        if (i < n4) {
            float4 v = reinterpret_cast<const float4*>(src)[i];
            reinterpret_cast<uint2*>(dst)[i] = cvt4(v);
        }
    }
}

// Merged W conversion: blockIdx.y selects Wq/Wk/Wv -> g_Wb[y]
__global__ void __launch_bounds__(256) conv_w_kernel(const float* __restrict__ Wq,
                                                     const float* __restrict__ Wk,
                                                     const float* __restrict__ Wv,
                                                     int n4) {
    const int z = blockIdx.y;
    const float* __restrict__ src = (z == 0) ? Wq : ((z == 1) ? Wk : Wv);
    __nv_bfloat16* __restrict__ dst = g_Wb[z];
    int i0 = blockIdx.x * 1024 + threadIdx.x;
#pragma unroll
    for (int j = 0; j < 4; j++) {
        int i = i0 + j * 256;
        if (i < n4) {
            float4 v = reinterpret_cast<const float4*>(src)[i];
            reinterpret_cast<uint2*>(dst)[i] = cvt4(v);
        }
    }
}

// ---------------------------------------------------------------------------
// Kernel 0b: pack adjacency int32 -> bitmask (warp ballot). One word / warp.
// ---------------------------------------------------------------------------
__global__ void __launch_bounds__(256) pack_adj_kernel(const int* __restrict__ adj) {
    size_t word = (size_t)blockIdx.x * 8 + (threadIdx.x >> 5);
    int lane = threadIdx.x & 31;
    int v = adj[word * 32 + lane];
    uint32_t m = __ballot_sync(0xFFFFFFFFu, v != 0);
    if (lane == 0) g_adjbits[word] = m;
}

// ---------------------------------------------------------------------------
// Kernel 1: QKV projection, bf16 mma + ldmatrix. Tile 128x128, 2-stage,
// k-stage 32 (round-12 form; superstage-64 is a recorded anti-pattern).
// grid = (DD/128, M_ROWS/128, 3), block 256 (8 warps, warp 32x64).
// ---------------------------------------------------------------------------
#define QP 20                       // words per 32-bf16 row (pitch 80B)
#define Q_STAGE (128 * QP)
#define Q_SMEM  (2 * 2 * Q_STAGE * 4)

__global__ void __launch_bounds__(256, 2) qkv_gemm_kernel(
    const float* __restrict__ bq, const float* __restrict__ bk,
    const float* __restrict__ bv)
{
    extern __shared__ uint32_t qsm[];
    const uint32_t smb = smem_u32(qsm);

    const int z = blockIdx.z;
    const __nv_bfloat16* __restrict__ W = g_Wb[z];
    const float* __restrict__ bias = (z == 0) ? bq : ((z == 1) ? bk : bv);
    __nv_bfloat16* __restrict__ outp = g_QKV[z];
    // Q pre-scale folds 1/sqrt(96) AND log2(e) (softmax uses exp2)
    const float oscale = (z == 0)
        ? 0.10206207261596577f * 1.4426950408889634f : 1.0f;

    const int n0 = blockIdx.x * 128;
    const int m0 = blockIdx.y * 128;
    const int t  = threadIdx.x;
    const int w  = t >> 5;
    const int lane = t & 31;
    const int g  = lane >> 2;
    const int t4 = lane & 3;
    const int m0w = (w & 3) * 32;
    const int n0w = (w >> 2) * 64;

    const uint32_t lml = (uint32_t)((lane & 15) * 80 + ((lane >> 4) & 1) * 16);

    const int sr = t >> 1;
    const int sch = (t & 1) * 2;

    auto issue = [&](int k0, int buf) {
        uint32_t ab = smb + buf * 2 * Q_STAGE * 4;
        uint32_t bb = ab + Q_STAGE * 4;
#pragma unroll
        for (int i = 0; i < 2; i++) {
            int ch = sch + i;
            cp16(ab + sr * 80 + ch * 16, g_Xb + (size_t)(m0 + sr) * DD + k0 + ch * 8);
            cp16(bb + sr * 80 + ch * 16, W    + (size_t)(n0 + sr) * DD + k0 + ch * 8);
        }
        cp_commit();
    };

    float acc[2][8][4];
#pragma unroll
    for (int i = 0; i < 2; i++)
#pragma unroll
        for (int j = 0; j < 8; j++)
#pragma unroll
            for (int e = 0; e < 4; e++) acc[i][j][e] = 0.0f;

    const int NIT = DD / 32;  // 24
    issue(0, 0);

    for (int it = 0; it < NIT; it++) {
        cp_wait0();
        __syncthreads();
        if (it + 1 < NIT) issue((it + 1) * 32, (it + 1) & 1);

        const uint32_t xsb = smb + (it & 1) * 2 * Q_STAGE * 4;
        const uint32_t wsb = xsb + Q_STAGE * 4;

#pragma unroll
        for (int ks = 0; ks < 2; ks++) {
            uint32_t a[2][4];
#pragma unroll
            for (int i = 0; i < 2; i++) {
                uint32_t addr = xsb + (uint32_t)((m0w + 16 * i) * 80 + ks * 32) + lml;
                ldsm_x4(a[i][0], a[i][1], a[i][2], a[i][3], addr);
            }
#pragma unroll
            for (int j2 = 0; j2 < 4; j2++) {
                uint32_t r0, r1, r2, r3;
                uint32_t addr = wsb + (uint32_t)((n0w + 16 * j2) * 80 + ks * 32) + lml;
                ldsm_x4(r0, r1, r2, r3, addr);
#pragma unroll
                for (int i = 0; i < 2; i++) {
                    mma_bf16(acc[i][2 * j2],     a[i], r0, r2);
                    mma_bf16(acc[i][2 * j2 + 1], a[i], r1, r3);
                }
            }
        }
    }

    // Epilogue: bias, optional Q scale, pack bf16 pairs, write [B,H,S,HD]
#pragma unroll
    for (int i = 0; i < 2; i++) {
        int rA = m0 + m0w + i * 16 + g;
        int rB = rA + 8;
        int bA = rA >> 11, sA = rA & (SS - 1);
        int bBv = rB >> 11, sB = rB & (SS - 1);
#pragma unroll
        for (int j = 0; j < 8; j++) {
            int c = n0 + n0w + j * 8 + 2 * t4;
            int h = c / HDIM;
            int d = c - h * HDIM;
            float b0 = bias[c], b1 = bias[c + 1];
            uint32_t vA = packbf((acc[i][j][0] + b0) * oscale, (acc[i][j][1] + b1) * oscale);
            uint32_t vB = packbf((acc[i][j][2] + b0) * oscale, (acc[i][j][3] + b1) * oscale);
            *reinterpret_cast<uint32_t*>(
                outp + (((size_t)(bA * HH + h)) * SS + sA) * HDIM + d) = vA;
            *reinterpret_cast<uint32_t*>(
                outp + (((size_t)(bBv * HH + h)) * SS + sB) * HDIM + d) = vB;
        }
    }
}

// ---------------------------------------------------------------------------
// Kernel 2: FA flash attention with UNSHIFTED exp2 softmax (Q pre-scaled by
// log2e/sqrt(96); masked -> ex2(-1e9) = 0). Register P, bit mask.
// QT=128, KT=64, 2-stage cp.async, K via ldmatrix, V via ldmatrix.trans.
// grid = (SS/128, HH, BB), block 256, 2 CTAs/SM.   (round-12 structure)
// ---------------------------------------------------------------------------
#define KPW 52                       // K/V smem pitch in words (208B row)
#define A_STAGE (2 * 64 * KPW)       // K + V words per stage
#define ATTN_BYTES (2 * A_STAGE * 4) // 53248

__global__ void __launch_bounds__(256, 2) attn_kernel()
{
    extern __shared__ uint32_t asm_[];
    const uint32_t smb = smem_u32(asm_);

    const int t    = threadIdx.x;
    const int w    = t >> 5;
    const int lane = t & 31;
    const int g    = lane >> 2;
    const int t4   = lane & 3;
    const int qt0  = blockIdx.x * 128;
    const int h    = blockIdx.y;
    const int b    = blockIdx.z;

    const __nv_bfloat16* __restrict__ Qb = g_QKV[0] + ((size_t)(b * HH + h)) * SS * HDIM;
    const __nv_bfloat16* __restrict__ Kb = g_QKV[1] + ((size_t)(b * HH + h)) * SS * HDIM;
    const __nv_bfloat16* __restrict__ Vb = g_QKV[2] + ((size_t)(b * HH + h)) * SS * HDIM;

    const int rAl = 16 * w + g;
    const int rBl = rAl + 8;
    const uint32_t* __restrict__ bitsA =
        g_adjbits + ((size_t)b * SS + qt0 + rAl) * (SS / 32);
    const uint32_t* __restrict__ bitsB =
        g_adjbits + ((size_t)b * SS + qt0 + rBl) * (SS / 32);

    // ---- Q fragments preloaded to registers (pre-scaled incl. log2e) ----
    uint32_t qa[6][4];
    {
        const uint32_t* qwA =
            reinterpret_cast<const uint32_t*>(Qb + (size_t)(qt0 + rAl) * HDIM);
        const uint32_t* qwB =
            reinterpret_cast<const uint32_t*>(Qb + (size_t)(qt0 + rBl) * HDIM);
#pragma unroll
        for (int ks = 0; ks < 6; ks++) {
            qa[ks][0] = qwA[8 * ks + t4];
            qa[ks][1] = qwB[8 * ks + t4];
            qa[ks][2] = qwA[8 * ks + 4 + t4];
            qa[ks][3] = qwB[8 * ks + 4 + t4];
        }
    }

    // ldmatrix lane offsets
    const uint32_t lmlK = (uint32_t)((lane & 15) * (KPW * 4) + ((lane >> 4) & 1) * 16);
    const int vk  = (lane & 7) + ((lane >> 3) & 1) * 8;
    const int vn  = ((lane >> 4) & 1) * 8;
    const uint32_t lmlV = (uint32_t)(vk * (KPW * 4) + vn * 2);

    float acc_o[12][4];
#pragma unroll
    for (int j = 0; j < 12; j++)
#pragma unroll
        for (int e = 0; e < 4; e++) acc_o[j][e] = 0.0f;
    float l0_ = 0.0f, l1_ = 0.0f;    // per-thread partial row sums

    auto issue = [&](int kt0, int buf) {
        uint32_t kb = smb + buf * A_STAGE * 4;
        uint32_t vb = kb + 64 * KPW * 4;
#pragma unroll
        for (int i = 0; i < 3; i++) {
            int e = t + i * 256;
            int r = e / 12, ch = e % 12;
            cp16(kb + r * (KPW * 4) + ch * 16, Kb + (size_t)(kt0 + r) * HDIM + ch * 8);
            cp16(vb + r * (KPW * 4) + ch * 16, Vb + (size_t)(kt0 + r) * HDIM + ch * 8);
        }
        cp_commit();
    };

    const int NKT = SS / 64;  // 32
    issue(0, 0);

    for (int kt = 0; kt < NKT; kt++) {
        cp_wait0();
        __syncthreads();
        if (kt + 1 < NKT) issue((kt + 1) * 64, (kt + 1) & 1);

        const uint32_t kbase = smb + (kt & 1) * A_STAGE * 4;
        const uint32_t vbase = kbase + 64 * KPW * 4 + lmlV;

        // mask bits (issued early; consumed after QK mma block)
        uint2 wA = *(const uint2*)(bitsA + 2 * kt);
        uint2 wB = *(const uint2*)(bitsB + 2 * kt);
        uint64_t bA = ((uint64_t)wA.y << 32) | wA.x;
        uint64_t bB = ((uint64_t)wB.y << 32) | wB.x;

        // ---- S = Q K^T : 16 rows x 64 keys per warp, 6 k16-steps ----
        float s_[8][4];
#pragma unroll
        for (int j = 0; j < 8; j++)
#pragma unroll
            for (int e = 0; e < 4; e++) s_[j][e] = 0.0f;

#pragma unroll
        for (int ks = 0; ks < 6; ks++) {
#pragma unroll
            for (int j2 = 0; j2 < 4; j2++) {
                uint32_t r0, r1, r2, r3;
                ldsm_x4(r0, r1, r2, r3,
                        kbase + (uint32_t)(16 * j2 * (KPW * 4) + ks * 32) + lmlK);
                mma_bf16(s_[2 * j2],     qa[ks], r0, r2);
                mma_bf16(s_[2 * j2 + 1], qa[ks], r1, r3);
            }
        }

        // ---- mask (bit extract) + unshifted ex2, packed in place ----
#pragma unroll
        for (int j = 0; j < 8; j++) {
            int sh = 8 * j + 2 * t4;
            if (!((bA >> sh) & 1))       s_[j][0] = -1e9f;
            if (!((bA >> (sh + 1)) & 1)) s_[j][1] = -1e9f;
            if (!((bB >> sh) & 1))       s_[j][2] = -1e9f;
            if (!((bB >> (sh + 1)) & 1)) s_[j][3] = -1e9f;
            float p0 = ex2_fast(s_[j][0]);
            float p1 = ex2_fast(s_[j][1]);
            float p2 = ex2_fast(s_[j][2]);
            float p3 = ex2_fast(s_[j][3]);
            l0_ += p0 + p1;
            l1_ += p2 + p3;
            s_[j][0] = __uint_as_float(packbf(p0, p1));
            s_[j][1] = __uint_as_float(packbf(p2, p3));
        }

        // ---- O += P V : P frags from score registers, V via ldmatrix.trans ----
#pragma unroll
        for (int ks = 0; ks < 4; ks++) {
            uint32_t a[4];
            a[0] = __float_as_uint(s_[2 * ks][0]);
            a[1] = __float_as_uint(s_[2 * ks][1]);
            a[2] = __float_as_uint(s_[2 * ks + 1][0]);
            a[3] = __float_as_uint(s_[2 * ks + 1][1]);
            uint32_t vrow = vbase + (uint32_t)(ks * 16 * KPW * 4);
#pragma unroll
            for (int j2 = 0; j2 < 6; j2++) {
                uint32_t v0, v1, v2, v3;
                ldsm_x4_t(v0, v1, v2, v3, vrow + j2 * 32);
                mma_bf16(acc_o[2 * j2],     a, v0, v1);
                mma_bf16(acc_o[2 * j2 + 1], a, v2, v3);
            }
        }
    }

    // ---- single end-of-loop row-sum reduction across the quad ----
    l0_ += __shfl_xor_sync(0xFFFFFFFFu, l0_, 1);
    l0_ += __shfl_xor_sync(0xFFFFFFFFu, l0_, 2);
    l1_ += __shfl_xor_sync(0xFFFFFFFFu, l1_, 1);
    l1_ += __shfl_xor_sync(0xFFFFFFFFu, l1_, 2);

    // ---- finalize: normalize and write context fp32 ----
    {
        float inv0 = 1.0f / l0_;
        float inv1 = 1.0f / l1_;
        float* oA = g_C + (size_t)(b * SS + qt0 + rAl) * DD + h * HDIM;
        float* oB = g_C + (size_t)(b * SS + qt0 + rBl) * DD + h * HDIM;
#pragma unroll
        for (int j = 0; j < 12; j++) {
            int c = j * 8 + 2 * t4;
            *reinterpret_cast<float2*>(oA + c) =
                make_float2(acc_o[j][0] * inv0, acc_o[j][1] * inv0);
            *reinterpret_cast<float2*>(oB + c) =
                make_float2(acc_o[j][2] * inv1, acc_o[j][3] * inv1);
        }
    }
}

// ---------------------------------------------------------------------------
// Kernel 3: residual + LayerNorm, float4 path, 2 rows per block.
// grid = 8192, block = 384 (warps 0-5 row0, warps 6-11 row1).
// ---------------------------------------------------------------------------
__global__ void __launch_bounds__(384) ln_kernel(
    const float* __restrict__ X,
    const float* __restrict__ gamma,
    const float* __restrict__ beta,
    float* __restrict__ out)
{
    const int t   = threadIdx.x;
    const int rsel = t / 192;             // 0 or 1
    const int tl  = t - rsel * 192;       // 0..191
    const int row = blockIdx.x * 2 + rsel;

    const float4* __restrict__ c4 = reinterpret_cast<const float4*>(g_C + (size_t)row * DD);
    const float4* __restrict__ x4 = reinterpret_cast<const float4*>(X  + (size_t)row * DD);

    float4 cv = c4[tl];
    float4 xv = x4[tl];
    float4 v = make_float4(cv.x + xv.x, cv.y + xv.y, cv.z + xv.z, cv.w + xv.w);
    float sum = v.x + v.y + v.z + v.w;
    float sq  = v.x * v.x + v.y * v.y + v.z * v.z + v.w * v.w;

#pragma unroll
    for (int o = 16; o > 0; o >>= 1) {
        sum += __shfl_xor_sync(0xFFFFFFFFu, sum, o);
        sq  += __shfl_xor_sync(0xFFFFFFFFu, sq, o);
    }
    __shared__ float rs_[12], rq_[12];
    int w = t >> 5, lane = t & 31;
    if (lane == 0) { rs_[w] = sum; rq_[w] = sq; }
    __syncthreads();
    sum = 0.0f; sq = 0.0f;
    int base = rsel * 6;
#pragma unroll
    for (int w2 = 0; w2 < 6; w2++) { sum += rs_[base + w2]; sq += rq_[base + w2]; }

    float mean = sum * (1.0f / 768.0f);
    float var  = sq * (1.0f / 768.0f) - mean * mean;
    float rstd = rsqrtf(var + 1e-5f);

    float4 gv = reinterpret_cast<const float4*>(gamma)[tl];
    float4 bv = reinterpret_cast<const float4*>(beta)[tl];
    float4 o;
    o.x = (v.x - mean) * rstd * gv.x + bv.x;
    o.y = (v.y - mean) * rstd * gv.y + bv.y;
    o.z = (v.z - mean) * rstd * gv.z + bv.z;
    o.w = (v.w - mean) * rstd * gv.w + bv.w;
    reinterpret_cast<float4*>(out + (size_t)row * DD)[tl] = o;
}

// ---------------------------------------------------------------------------
extern "C" void kernel_launch(void* const* d_in, const int* in_sizes, int n_in,
                              void* d_out, int out_size)
{
    const float* X     = (const float*)d_in[0];
    const int*   adj   = (const int*)  d_in[1];
    const float* Wq    = (const float*)d_in[2];
    const float* bq    = (const float*)d_in[3];
    const float* Wk    = (const float*)d_in[4];
    const float* bk    = (const float*)d_in[5];
    const float* Wv    = (const float*)d_in[6];
    const float* bv    = (const float*)d_in[7];
    const float* gamma = (const float*)d_in[8];
    const float* beta  = (const float*)d_in[9];
    float* out = (float*)d_out;

    __nv_bfloat16 *xb_p;
    cudaGetSymbolAddress((void**)&xb_p, g_Xb);

    const int nX4 = M_ROWS * DD / 4;   // 3,145,728
    const int nW4 = DD * DD / 4;       // 147,456
    conv_x_kernel<<<(nX4 + 1023) / 1024, 256>>>(X, xb_p, nX4);
    {
        dim3 gw((nW4 + 1023) / 1024, 3);
        conv_w_kernel<<<gw, 256>>>(Wq, Wk, Wv, nW4);
    }

    pack_adj_kernel<<<(BB * SS * (SS / 32)) / 8, 256>>>(adj);

    cudaFuncSetAttribute(qkv_gemm_kernel,
                         cudaFuncAttributeMaxDynamicSharedMemorySize, Q_SMEM);
    dim3 gg(DD / 128, M_ROWS / 128, 3);
    qkv_gemm_kernel<<<gg, 256, Q_SMEM>>>(bq, bk, bv);

    cudaFuncSetAttribute(attn_kernel,
                         cudaFuncAttributeMaxDynamicSharedMemorySize, ATTN_BYTES);
    dim3 ga(SS / 128, HH, BB);
    attn_kernel<<<ga, 256, ATTN_BYTES>>>();

    ln_kernel<<<M_ROWS / 2, 384>>>(X, gamma, beta, out);
}